// round 4
// baseline (speedup 1.0000x reference)
#include <cuda_runtime.h>
#include <math.h>

#define B 64
#define T 128
#define V 25
#define C 128
#define K 128
#define R 32

// ---------------- scratch (device globals; no allocations allowed) ----------
__device__ float g_xbar[B*V*C];
__device__ float g_phi [B*V*K];
__device__ float g_theta[B*V*K];
__device__ float g_Hbar[B*V*K];
__device__ float g_Atil[B*V*V*K];      // [b][u][v][k]
__device__ float g_gate[B*K];
__device__ float g_H[B*T*V*K];         // [b][t][v][k]

// f32x2 packed FMA (SASS FFMA2) -- exact fp32, 2x rate
__device__ __forceinline__ unsigned long long fma2(unsigned long long a,
                                                   unsigned long long b,
                                                   unsigned long long c) {
    unsigned long long d;
    asm("fma.rn.f32x2 %0, %1, %2, %3;" : "=l"(d) : "l"(a), "l"(b), "l"(c));
    return d;
}
__device__ __forceinline__ void unpack2(unsigned long long p, float& lo, float& hi) {
    asm("mov.b64 {%0,%1}, %2;" : "=f"(lo), "=f"(hi) : "l"(p));
}

// ---------------- K1: xbar = mean_t x  --------------------------------------
__global__ void k1_xbar(const float* __restrict__ x) {
    int bv = blockIdx.x;
    int c  = threadIdx.x;
    int b = bv / V, v = bv % V;
    const float* p = x + ((size_t)(b*T)*V + v)*C + c;
    float acc = 0.f;
#pragma unroll 8
    for (int t = 0; t < T; t++) acc += p[(size_t)t*V*C];
    g_xbar[bv*C + c] = acc * (1.0f/T);
}

// ---------------- K2: phi_x / theta_x / Hbar  (xbar @ W + b) ----------------
__global__ void k2_small(const float* __restrict__ pw, const float* __restrict__ pb,
                         const float* __restrict__ tw, const float* __restrict__ tb,
                         const float* __restrict__ xw, const float* __restrict__ xb2) {
    extern __shared__ float sm2[];
    float* xb_s = sm2;            // 3200
    float* W_s  = sm2 + 3200;     // 16384
    int b = blockIdx.x, tid = threadIdx.x;
    for (int lin = tid; lin < V*C; lin += 256) xb_s[lin] = g_xbar[b*V*C + lin];

    const float* Wp[3] = {pw, tw, xw};
    const float* Bp[3] = {pb, tb, xb2};
    float* Op[3];
    Op[0] = g_phi; Op[1] = g_theta; Op[2] = g_Hbar;

    for (int w = 0; w < 3; w++) {
        for (int lin = tid; lin < C*K; lin += 256) W_s[lin] = Wp[w][lin];
        __syncthreads();
        for (int task = tid; task < V*(K/4); task += 256) {
            int v  = task >> 5;
            int k4 = (task & 31) << 2;
            float4 acc = *(const float4*)&Bp[w][k4];
            for (int c = 0; c < C; c++) {
                float a = xb_s[v*C + c];
                float4 wv = *(const float4*)&W_s[c*K + k4];
                acc.x += a*wv.x; acc.y += a*wv.y; acc.z += a*wv.z; acc.w += a*wv.w;
            }
            *(float4*)&Op[w][b*V*K + v*K + k4] = acc;
        }
        __syncthreads();
    }
}

// ---------------- K3: A_tilde[b][u][v][k] = A[k,u,v] + lam*(F@kappa + b) ----
#define PAIRS_PER_BLK 32
#define FPAD 132
__global__ void k3_atilde(const float* __restrict__ A, const float* __restrict__ lam_p,
                          const float* __restrict__ kw, const float* __restrict__ kb) {
    extern __shared__ float sm3[];
    float* kap_s = sm3;                 // 16384
    float* F_s   = sm3 + C*K;           // 32*132
    int b = blockIdx.x / 20;
    int chunk = blockIdx.x % 20;
    int tid = threadIdx.x;

    for (int lin = tid; lin < K*K; lin += 256) kap_s[lin] = kw[lin];

    for (int idx = tid; idx < PAIRS_PER_BLK*K; idx += 256) {
        int p = idx >> 7, m = idx & 127;
        int pair = chunk*PAIRS_PER_BLK + p;
        float f = 0.f;
        if (pair < V*V) {
            int i = pair / V, j = pair % V;
            f = tanhf(g_phi[(b*V+i)*K + m] - g_theta[(b*V+j)*K + m]);
        }
        F_s[p*FPAD + m] = f;
    }
    __syncthreads();

    int wid = tid >> 5, lane = tid & 31;
    int k0 = wid * 16;
    int pair = chunk*PAIRS_PER_BLK + lane;
    if (pair >= V*V) return;

    float acc[16];
#pragma unroll
    for (int q = 0; q < 16; q++) acc[q] = 0.f;

    for (int m = 0; m < K; m += 4) {
        float4 f4 = *(const float4*)&F_s[lane*FPAD + m];
#pragma unroll
        for (int g = 0; g < 4; g++) {
            float4 r0 = *(const float4*)&kap_s[(m+0)*K + k0 + g*4];
            float4 r1 = *(const float4*)&kap_s[(m+1)*K + k0 + g*4];
            float4 r2 = *(const float4*)&kap_s[(m+2)*K + k0 + g*4];
            float4 r3 = *(const float4*)&kap_s[(m+3)*K + k0 + g*4];
            acc[g*4+0] += f4.x*r0.x + f4.y*r1.x + f4.z*r2.x + f4.w*r3.x;
            acc[g*4+1] += f4.x*r0.y + f4.y*r1.y + f4.z*r2.y + f4.w*r3.y;
            acc[g*4+2] += f4.x*r0.z + f4.y*r1.z + f4.z*r2.z + f4.w*r3.z;
            acc[g*4+3] += f4.x*r0.w + f4.y*r1.w + f4.z*r2.w + f4.w*r3.w;
        }
    }

    float lamv = *lam_p;
    int i = pair / V, j = pair % V;
    int outbase = ((b*V + i)*V + j)*K + k0;
#pragma unroll
    for (int g = 0; g < 4; g++) {
        float4 r;
        int kk = k0 + g*4;
        r.x = A[((kk+0)*V + i)*V + j] + lamv*(acc[g*4+0] + kb[kk+0]);
        r.y = A[((kk+1)*V + i)*V + j] + lamv*(acc[g*4+1] + kb[kk+1]);
        r.z = A[((kk+2)*V + i)*V + j] + lamv*(acc[g*4+2] + kb[kk+2]);
        r.w = A[((kk+3)*V + i)*V + j] + lamv*(acc[g*4+3] + kb[kk+3]);
        *(float4*)&g_Atil[outbase + g*4] = r;
    }
}

// ---------------- K4: gate[b][k]  -------------------------------------------
__global__ void __launch_bounds__(512) k4_gate(
        const float* __restrict__ qw, const float* __restrict__ qb,
        const float* __restrict__ kw, const float* __restrict__ kb,
        const float* __restrict__ c1w, const float* __restrict__ c1b,
        const float* __restrict__ l1w, const float* __restrict__ l1b,
        const float* __restrict__ c2w, const float* __restrict__ c2b) {
    extern __shared__ float sm4[];
    float* Hb_s = sm4;                 // 3200
    float* Zb_s = Hb_s + 3200;         // 3200
    float* XQ_s = Zb_s + 3200;         // 3200
    float* XK_s = XQ_s + 3200;         // 3200
    float* qw_s = XK_s + 3200;         // 4096
    float* kw_s = qw_s + 4096;         // 4096
    float* ca_s = kw_s + 4096;         // 512
    float* c1_s = ca_s + 512;          // 32

    int b = blockIdx.x, tid = threadIdx.x;
    int k = tid & 127, uh = tid >> 7;
    for (int lin = tid; lin < V*K; lin += 512) Hb_s[lin] = g_Hbar[b*V*K + lin];
    __syncthreads();

    int u_lo = (uh == 0) ? 0 : (7 + 6*(uh-1));
    int nu   = (uh == 0) ? 7 : 6;

    for (int ui = 0; ui < nu; ui++) {
        int u = u_lo + ui;
        float acc = 0.f;
        const float* ap = g_Atil + ((size_t)(b*V + u)*V)*K + k;
#pragma unroll
        for (int v = 0; v < V; v++) acc += ap[v*K] * Hb_s[v*K + k];
        Zb_s[u*K + k] = acc;
    }
    __syncthreads();

    float accq[7], acck[7];
    for (int ui = 0; ui < nu; ui++) { accq[ui] = qb[k]; acck[ui] = kb[k]; }
    for (int mc = 0; mc < K; mc += 32) {
        for (int lin = tid; lin < 32*128; lin += 512) {
            int mm = lin >> 7, kk = lin & 127;
            qw_s[lin] = qw[(mc + mm)*K + kk];
            kw_s[lin] = kw[(mc + mm)*K + kk];
        }
        __syncthreads();
        for (int ui = 0; ui < nu; ui++) {
            int u = u_lo + ui;
            float aq = accq[ui], ak = acck[ui];
#pragma unroll
            for (int mm = 0; mm < 32; mm++) {
                float z = Zb_s[u*K + mc + mm];
                aq += z * qw_s[mm*128 + k];
                ak += z * kw_s[mm*128 + k];
            }
            accq[ui] = aq; acck[ui] = ak;
        }
        __syncthreads();
    }
    for (int ui = 0; ui < nu; ui++) {
        XQ_s[(u_lo+ui)*K + k] = accq[ui];
        XK_s[(u_lo+ui)*K + k] = acck[ui];
    }
    __syncthreads();

    const float inv_scale = 1.0f / sqrtf((float)T);
    float ca = 0.f;
    for (int ui = 0; ui < nu; ui++) {
        int u = u_lo + ui;
        float xq = XQ_s[u*K + k];
        float mx = -1e30f;
#pragma unroll
        for (int v = 0; v < V; v++) {
            float s = xq * XK_s[v*K + k] * inv_scale;
            mx = fmaxf(mx, s);
        }
        float den = 0.f, num = 0.f;
#pragma unroll
        for (int v = 0; v < V; v++) {
            float s = xq * XK_s[v*K + k] * inv_scale;
            float e = expf(s - mx);
            den += e;
            num += e * Hb_s[v*K + k];
        }
        ca += num / den;
    }
    ca_s[tid] = ca;
    __syncthreads();
    if (tid < 128)
        ca_s[tid] = (ca_s[tid] + ca_s[tid+128] + ca_s[tid+256] + ca_s[tid+384]) * (1.0f/V);
    __syncthreads();

    if (tid < R) {
        float t = c1b[tid];
        for (int kk = 0; kk < K; kk++) t += ca_s[kk] * c1w[kk*R + tid];
        float mu = t;
#pragma unroll
        for (int o = 16; o > 0; o >>= 1) mu += __shfl_xor_sync(0xffffffffu, mu, o);
        mu *= (1.0f/R);
        float d = t - mu;
        float var = d*d;
#pragma unroll
        for (int o = 16; o > 0; o >>= 1) var += __shfl_xor_sync(0xffffffffu, var, o);
        var *= (1.0f/R);
        float y = d * rsqrtf(var + 1e-5f) * l1w[tid] + l1b[tid];
        c1_s[tid] = 0.5f * y * (1.0f + erff(y * 0.70710678118654752f));
    }
    __syncthreads();

    if (tid < 128) {
        float g = c2b[k];
#pragma unroll
        for (int r = 0; r < R; r++) g += c1_s[r] * c2w[r*K + k];
        g_gate[b*K + k] = 1.0f / (1.0f + expf(-g));
    }
}

// ---------------- K5: H = x @ xi_w + b  (f32x2 GEMM, 128x128 tile) ----------
__global__ void __launch_bounds__(256, 2) k5_hgemm(const float* __restrict__ x,
                                                   const float* __restrict__ xiw,
                                                   const float* __restrict__ xib) {
    __shared__ float xs[16*256];   // [c][2r] -- each x scalar duplicated
    __shared__ float ws[16*128];   // [c][k]
    int tid = threadIdx.x;
    int tx = tid & 15, ty = tid >> 4;
    size_t row0 = (size_t)blockIdx.x * 128;

    unsigned long long acc[8][4];
#pragma unroll
    for (int i = 0; i < 8; i++)
#pragma unroll
        for (int j = 0; j < 4; j++) acc[i][j] = 0ull;

    for (int cc = 0; cc < C; cc += 16) {
        for (int lin = tid; lin < 2048; lin += 256) {
            int r = lin >> 4, c = lin & 15;
            float vx = x[(row0 + r)*C + cc + c];
            xs[c*256 + 2*r]     = vx;
            xs[c*256 + 2*r + 1] = vx;
        }
        for (int lin = tid; lin < 2048; lin += 256) {
            int c = lin >> 7, kk = lin & 127;
            ws[lin] = xiw[(cc + c)*K + kk];
        }
        __syncthreads();
#pragma unroll
        for (int c = 0; c < 16; c++) {
            // 8 dup-pairs (rows ty*8..ty*8+7) via 4x LDS.128 (broadcast groups)
            ulonglong2 a01 = *(const ulonglong2*)&xs[c*256 + ty*16];
            ulonglong2 a23 = *(const ulonglong2*)&xs[c*256 + ty*16 + 4];
            ulonglong2 a45 = *(const ulonglong2*)&xs[c*256 + ty*16 + 8];
            ulonglong2 a67 = *(const ulonglong2*)&xs[c*256 + ty*16 + 12];
            // 4 w-pairs (cols tx*8..tx*8+7) via 2x LDS.128
            ulonglong2 w01 = *(const ulonglong2*)&ws[c*128 + tx*8];
            ulonglong2 w23 = *(const ulonglong2*)&ws[c*128 + tx*8 + 4];
            unsigned long long av[8] = {a01.x, a01.y, a23.x, a23.y,
                                        a45.x, a45.y, a67.x, a67.y};
            unsigned long long wv[4] = {w01.x, w01.y, w23.x, w23.y};
#pragma unroll
            for (int i = 0; i < 8; i++) {
                acc[i][0] = fma2(av[i], wv[0], acc[i][0]);
                acc[i][1] = fma2(av[i], wv[1], acc[i][1]);
                acc[i][2] = fma2(av[i], wv[2], acc[i][2]);
                acc[i][3] = fma2(av[i], wv[3], acc[i][3]);
            }
        }
        __syncthreads();
    }

    float4 b0 = *(const float4*)&xib[tx*8];
    float4 b1 = *(const float4*)&xib[tx*8 + 4];
#pragma unroll
    for (int i = 0; i < 8; i++) {
        size_t row = row0 + ty*8 + i;
        float f0,f1,f2,f3,f4v,f5,f6,f7;
        unpack2(acc[i][0], f0, f1);
        unpack2(acc[i][1], f2, f3);
        unpack2(acc[i][2], f4v, f5);
        unpack2(acc[i][3], f6, f7);
        float4 o0, o1;
        o0.x = f0 + b0.x; o0.y = f1 + b0.y; o0.z = f2 + b0.z; o0.w = f3 + b0.w;
        o1.x = f4v + b1.x; o1.y = f5 + b1.y; o1.z = f6 + b1.z; o1.w = f7 + b1.w;
        *(float4*)&g_H[row*K + tx*8]     = o0;
        *(float4*)&g_H[row*K + tx*8 + 4] = o1;
    }
}

// ---------------- K6: Z_G = gate*(A_tilde . H) + LayerNorm (f32x2) ----------
#define TT 8
__global__ void __launch_bounds__(512, 1) k6_zg_ln(const float* __restrict__ l2w,
                                                   const float* __restrict__ l2b,
                                                   float* __restrict__ out) {
    extern __shared__ float sm6[];
    float* Hs   = sm6;                 // 200*128 = 25600
    float* As0  = Hs  + 25600;         // 3200
    float* As1  = As0 + 3200;          // 3200
    float* mu_s = As1 + 3200;          // 200
    float* rs_s = mu_s + 200;          // 200

    int b  = blockIdx.x >> 4;
    int tt = blockIdx.x & 15;
    int tid = threadIdx.x;
    int kp = tid & 63;                 // k-pair index (k = 2*kp, 2*kp+1)
    int tg = tid >> 6;                 // local t (0..7)

    const size_t base = ((size_t)(b*T + tt*TT))*V*K;

    for (int lin = tid; lin < TT*V*K; lin += 512)
        Hs[lin] = g_H[base + lin];

    const float* Ab = g_Atil + (size_t)b*V*V*K;
    for (int lin = tid; lin < V*K; lin += 512) {
        int u = lin >> 7, kk = lin & 127;
        As0[lin] = Ab[((size_t)u*V + 0)*K + kk];
    }
    __syncthreads();

    unsigned long long z[V];
#pragma unroll
    for (int u = 0; u < V; u++) z[u] = 0ull;

    for (int v = 0; v < V; v++) {
        float* cur = (v & 1) ? As1 : As0;
        float* nxt = (v & 1) ? As0 : As1;
        if (v + 1 < V) {
            for (int lin = tid; lin < V*K; lin += 512) {
                int u = lin >> 7, kk = lin & 127;
                nxt[lin] = Ab[((size_t)u*V + (v+1))*K + kk];
            }
        }
        unsigned long long h = *(const unsigned long long*)&Hs[(tg*V + v)*K + 2*kp];
#pragma unroll
        for (int u = 0; u < V; u++) {
            unsigned long long a = *(const unsigned long long*)&cur[u*K + 2*kp];
            z[u] = fma2(h, a, z[u]);
        }
        __syncthreads();
    }

    // gate and write Z back to Hs (H no longer needed)
    float2 gk = *(const float2*)&g_gate[b*K + 2*kp];
#pragma unroll
    for (int u = 0; u < V; u++) {
        float zl, zh;
        unpack2(z[u], zl, zh);
        Hs[(tg*V + u)*K + 2*kp]     = zl * gk.x;
        Hs[(tg*V + u)*K + 2*kp + 1] = zh * gk.y;
    }
    __syncthreads();

    // LayerNorm stats (rotated k-scan: conflict-free)
    for (int p = tid; p < TT*V; p += 512) {
        float s = 0.f, s2 = 0.f;
        for (int kk = 0; kk < K; kk++) {
            int k = (kk + p) & 127;
            float val = Hs[p*K + k];
            s += val; s2 += val*val;
        }
        float m = s * (1.0f/K);
        float var = s2 * (1.0f/K) - m*m;
        mu_s[p] = m;
        rs_s[p] = rsqrtf(var + 1e-5f);
    }
    __syncthreads();

    for (int lin = tid; lin < TT*V*K; lin += 512) {
        int r = lin >> 7, kk = lin & 127;
        float val = (Hs[lin] - mu_s[r]) * rs_s[r];
        out[base + lin] = val * l2w[kk] + l2b[kk];
    }
}

// ---------------- launch --------------------------------------------------
extern "C" void kernel_launch(void* const* d_in, const int* in_sizes, int n_in,
                              void* d_out, int out_size) {
    const float* x    = (const float*)d_in[0];
    const float* A    = (const float*)d_in[1];
    const float* lam  = (const float*)d_in[2];
    const float* phiw = (const float*)d_in[3];
    const float* phib = (const float*)d_in[4];
    const float* thw  = (const float*)d_in[5];
    const float* thb  = (const float*)d_in[6];
    const float* kapw = (const float*)d_in[7];
    const float* kapb = (const float*)d_in[8];
    const float* xiw  = (const float*)d_in[9];
    const float* xib  = (const float*)d_in[10];
    const float* qw   = (const float*)d_in[11];
    const float* qb   = (const float*)d_in[12];
    const float* kw   = (const float*)d_in[13];
    const float* kb   = (const float*)d_in[14];
    const float* c1w  = (const float*)d_in[15];
    const float* c1b  = (const float*)d_in[16];
    const float* l1w  = (const float*)d_in[17];
    const float* l1b  = (const float*)d_in[18];
    const float* c2w  = (const float*)d_in[19];
    const float* c2b  = (const float*)d_in[20];
    const float* l2w  = (const float*)d_in[21];
    const float* l2b  = (const float*)d_in[22];
    float* out = (float*)d_out;

    size_t sm2 = (size_t)(3200 + 16384) * 4;
    size_t sm3 = (size_t)(16384 + 32*FPAD) * 4;
    size_t sm4 = (size_t)(4*3200 + 2*4096 + 512 + 32) * 4;
    size_t sm6 = (size_t)(25600 + 3200 + 3200 + 200 + 200) * 4;

    cudaFuncSetAttribute(k2_small,  cudaFuncAttributeMaxDynamicSharedMemorySize, (int)sm2);
    cudaFuncSetAttribute(k3_atilde, cudaFuncAttributeMaxDynamicSharedMemorySize, (int)sm3);
    cudaFuncSetAttribute(k4_gate,   cudaFuncAttributeMaxDynamicSharedMemorySize, (int)sm4);
    cudaFuncSetAttribute(k6_zg_ln,  cudaFuncAttributeMaxDynamicSharedMemorySize, (int)sm6);

    k1_xbar<<<B*V, 128>>>(x);
    k2_small<<<B, 256, sm2>>>(phiw, phib, thw, thb, xiw, xib);
    k3_atilde<<<B*20, 256, sm3>>>(A, lam, kapw, kapb);
    k4_gate<<<B, 512, sm4>>>(qw, qb, kw, kb, c1w, c1b, l1w, l1b, c2w, c2b);
    k5_hgemm<<<(B*T*V)/128, 256>>>(x, xiw, xib);
    k6_zg_ln<<<B*16, 512, sm6>>>(l2w, l2b, out);
}

// round 5
// speedup vs baseline: 1.0218x; 1.0218x over previous
#include <cuda_runtime.h>
#include <math.h>

#define B 64
#define T 128
#define V 25
#define C 128
#define K 128
#define R 32

// ---------------- scratch (device globals; no allocations allowed) ----------
__device__ float g_xbar[B*V*C];
__device__ float g_phi [B*V*K];
__device__ float g_theta[B*V*K];
__device__ float g_Hbar[B*V*K];
__device__ float g_Atil[B*V*V*K];      // [b][u][v][k]
__device__ float g_gate[B*K];
__device__ float g_H[B*T*V*K];         // [b][t][v][k]

// f32x2 packed FMA (SASS FFMA2) -- exact fp32, 2x rate
__device__ __forceinline__ unsigned long long fma2(unsigned long long a,
                                                   unsigned long long b,
                                                   unsigned long long c) {
    unsigned long long d;
    asm("fma.rn.f32x2 %0, %1, %2, %3;" : "=l"(d) : "l"(a), "l"(b), "l"(c));
    return d;
}
__device__ __forceinline__ void unpack2(unsigned long long p, float& lo, float& hi) {
    asm("mov.b64 {%0,%1}, %2;" : "=f"(lo), "=f"(hi) : "l"(p));
}

// ---------------- K1: xbar = mean_t x  --------------------------------------
__global__ void k1_xbar(const float* __restrict__ x) {
    int bv = blockIdx.x;
    int c  = threadIdx.x;
    int b = bv / V, v = bv % V;
    const float* p = x + ((size_t)(b*T)*V + v)*C + c;
    float acc = 0.f;
#pragma unroll 8
    for (int t = 0; t < T; t++) acc += p[(size_t)t*V*C];
    g_xbar[bv*C + c] = acc * (1.0f/T);
}

// ---------------- K2: phi_x / theta_x / Hbar  (xbar @ W + b) ----------------
__global__ void k2_small(const float* __restrict__ pw, const float* __restrict__ pb,
                         const float* __restrict__ tw, const float* __restrict__ tb,
                         const float* __restrict__ xw, const float* __restrict__ xb2) {
    extern __shared__ float sm2[];
    float* xb_s = sm2;            // 3200
    float* W_s  = sm2 + 3200;     // 16384
    int b = blockIdx.x, tid = threadIdx.x;
    for (int lin = tid; lin < V*C; lin += 256) xb_s[lin] = g_xbar[b*V*C + lin];

    const float* Wp[3] = {pw, tw, xw};
    const float* Bp[3] = {pb, tb, xb2};
    float* Op[3];
    Op[0] = g_phi; Op[1] = g_theta; Op[2] = g_Hbar;

    for (int w = 0; w < 3; w++) {
        for (int lin = tid; lin < C*K; lin += 256) W_s[lin] = Wp[w][lin];
        __syncthreads();
        for (int task = tid; task < V*(K/4); task += 256) {
            int v  = task >> 5;
            int k4 = (task & 31) << 2;
            float4 acc = *(const float4*)&Bp[w][k4];
            for (int c = 0; c < C; c++) {
                float a = xb_s[v*C + c];
                float4 wv = *(const float4*)&W_s[c*K + k4];
                acc.x += a*wv.x; acc.y += a*wv.y; acc.z += a*wv.z; acc.w += a*wv.w;
            }
            *(float4*)&Op[w][b*V*K + v*K + k4] = acc;
        }
        __syncthreads();
    }
}

// ---------------- K3: A_tilde[b][u][v][k] = A[k,u,v] + lam*(F@kappa + b) ----
#define PAIRS_PER_BLK 32
#define FPAD 132
__global__ void k3_atilde(const float* __restrict__ A, const float* __restrict__ lam_p,
                          const float* __restrict__ kw, const float* __restrict__ kb) {
    extern __shared__ float sm3[];
    float* kap_s = sm3;                 // 16384
    float* F_s   = sm3 + C*K;           // 32*132
    int b = blockIdx.x / 20;
    int chunk = blockIdx.x % 20;
    int tid = threadIdx.x;

    for (int lin = tid; lin < K*K; lin += 256) kap_s[lin] = kw[lin];

    for (int idx = tid; idx < PAIRS_PER_BLK*K; idx += 256) {
        int p = idx >> 7, m = idx & 127;
        int pair = chunk*PAIRS_PER_BLK + p;
        float f = 0.f;
        if (pair < V*V) {
            int i = pair / V, j = pair % V;
            f = tanhf(g_phi[(b*V+i)*K + m] - g_theta[(b*V+j)*K + m]);
        }
        F_s[p*FPAD + m] = f;
    }
    __syncthreads();

    int wid = tid >> 5, lane = tid & 31;
    int k0 = wid * 16;
    int pair = chunk*PAIRS_PER_BLK + lane;
    if (pair >= V*V) return;

    float acc[16];
#pragma unroll
    for (int q = 0; q < 16; q++) acc[q] = 0.f;

    for (int m = 0; m < K; m += 4) {
        float4 f4 = *(const float4*)&F_s[lane*FPAD + m];
#pragma unroll
        for (int g = 0; g < 4; g++) {
            float4 r0 = *(const float4*)&kap_s[(m+0)*K + k0 + g*4];
            float4 r1 = *(const float4*)&kap_s[(m+1)*K + k0 + g*4];
            float4 r2 = *(const float4*)&kap_s[(m+2)*K + k0 + g*4];
            float4 r3 = *(const float4*)&kap_s[(m+3)*K + k0 + g*4];
            acc[g*4+0] += f4.x*r0.x + f4.y*r1.x + f4.z*r2.x + f4.w*r3.x;
            acc[g*4+1] += f4.x*r0.y + f4.y*r1.y + f4.z*r2.y + f4.w*r3.y;
            acc[g*4+2] += f4.x*r0.z + f4.y*r1.z + f4.z*r2.z + f4.w*r3.z;
            acc[g*4+3] += f4.x*r0.w + f4.y*r1.w + f4.z*r2.w + f4.w*r3.w;
        }
    }

    float lamv = *lam_p;
    int i = pair / V, j = pair % V;
    int outbase = ((b*V + i)*V + j)*K + k0;
#pragma unroll
    for (int g = 0; g < 4; g++) {
        float4 r;
        int kk = k0 + g*4;
        r.x = A[((kk+0)*V + i)*V + j] + lamv*(acc[g*4+0] + kb[kk+0]);
        r.y = A[((kk+1)*V + i)*V + j] + lamv*(acc[g*4+1] + kb[kk+1]);
        r.z = A[((kk+2)*V + i)*V + j] + lamv*(acc[g*4+2] + kb[kk+2]);
        r.w = A[((kk+3)*V + i)*V + j] + lamv*(acc[g*4+3] + kb[kk+3]);
        *(float4*)&g_Atil[outbase + g*4] = r;
    }
}

// ---------------- K4: gate[b][k]  -------------------------------------------
__global__ void __launch_bounds__(512) k4_gate(
        const float* __restrict__ qw, const float* __restrict__ qb,
        const float* __restrict__ kw, const float* __restrict__ kb,
        const float* __restrict__ c1w, const float* __restrict__ c1b,
        const float* __restrict__ l1w, const float* __restrict__ l1b,
        const float* __restrict__ c2w, const float* __restrict__ c2b) {
    extern __shared__ float sm4[];
    float* Hb_s = sm4;                 // 3200
    float* Zb_s = Hb_s + 3200;         // 3200
    float* XQ_s = Zb_s + 3200;         // 3200
    float* XK_s = XQ_s + 3200;         // 3200
    float* qw_s = XK_s + 3200;         // 4096
    float* kw_s = qw_s + 4096;         // 4096
    float* ca_s = kw_s + 4096;         // 512
    float* c1_s = ca_s + 512;          // 32

    int b = blockIdx.x, tid = threadIdx.x;
    int k = tid & 127, uh = tid >> 7;
    for (int lin = tid; lin < V*K; lin += 512) Hb_s[lin] = g_Hbar[b*V*K + lin];
    __syncthreads();

    int u_lo = (uh == 0) ? 0 : (7 + 6*(uh-1));
    int nu   = (uh == 0) ? 7 : 6;

    for (int ui = 0; ui < nu; ui++) {
        int u = u_lo + ui;
        float acc = 0.f;
        const float* ap = g_Atil + ((size_t)(b*V + u)*V)*K + k;
#pragma unroll
        for (int v = 0; v < V; v++) acc += ap[v*K] * Hb_s[v*K + k];
        Zb_s[u*K + k] = acc;
    }
    __syncthreads();

    float accq[7], acck[7];
    for (int ui = 0; ui < nu; ui++) { accq[ui] = qb[k]; acck[ui] = kb[k]; }
    for (int mc = 0; mc < K; mc += 32) {
        for (int lin = tid; lin < 32*128; lin += 512) {
            int mm = lin >> 7, kk = lin & 127;
            qw_s[lin] = qw[(mc + mm)*K + kk];
            kw_s[lin] = kw[(mc + mm)*K + kk];
        }
        __syncthreads();
        for (int ui = 0; ui < nu; ui++) {
            int u = u_lo + ui;
            float aq = accq[ui], ak = acck[ui];
#pragma unroll
            for (int mm = 0; mm < 32; mm++) {
                float z = Zb_s[u*K + mc + mm];
                aq += z * qw_s[mm*128 + k];
                ak += z * kw_s[mm*128 + k];
            }
            accq[ui] = aq; acck[ui] = ak;
        }
        __syncthreads();
    }
    for (int ui = 0; ui < nu; ui++) {
        XQ_s[(u_lo+ui)*K + k] = accq[ui];
        XK_s[(u_lo+ui)*K + k] = acck[ui];
    }
    __syncthreads();

    const float inv_scale = 1.0f / sqrtf((float)T);
    float ca = 0.f;
    for (int ui = 0; ui < nu; ui++) {
        int u = u_lo + ui;
        float xq = XQ_s[u*K + k];
        float mx = -1e30f;
#pragma unroll
        for (int v = 0; v < V; v++) {
            float s = xq * XK_s[v*K + k] * inv_scale;
            mx = fmaxf(mx, s);
        }
        float den = 0.f, num = 0.f;
#pragma unroll
        for (int v = 0; v < V; v++) {
            float s = xq * XK_s[v*K + k] * inv_scale;
            float e = expf(s - mx);
            den += e;
            num += e * Hb_s[v*K + k];
        }
        ca += num / den;
    }
    ca_s[tid] = ca;
    __syncthreads();
    if (tid < 128)
        ca_s[tid] = (ca_s[tid] + ca_s[tid+128] + ca_s[tid+256] + ca_s[tid+384]) * (1.0f/V);
    __syncthreads();

    if (tid < R) {
        float t = c1b[tid];
        for (int kk = 0; kk < K; kk++) t += ca_s[kk] * c1w[kk*R + tid];
        float mu = t;
#pragma unroll
        for (int o = 16; o > 0; o >>= 1) mu += __shfl_xor_sync(0xffffffffu, mu, o);
        mu *= (1.0f/R);
        float d = t - mu;
        float var = d*d;
#pragma unroll
        for (int o = 16; o > 0; o >>= 1) var += __shfl_xor_sync(0xffffffffu, var, o);
        var *= (1.0f/R);
        float y = d * rsqrtf(var + 1e-5f) * l1w[tid] + l1b[tid];
        c1_s[tid] = 0.5f * y * (1.0f + erff(y * 0.70710678118654752f));
    }
    __syncthreads();

    if (tid < 128) {
        float g = c2b[k];
#pragma unroll
        for (int r = 0; r < R; r++) g += c1_s[r] * c2w[r*K + k];
        g_gate[b*K + k] = 1.0f / (1.0f + expf(-g));
    }
}

// ---------------- K5: H = x @ xi_w + b  (f32x2 GEMM, 128x128 tile) ----------
__global__ void __launch_bounds__(256, 2) k5_hgemm(const float* __restrict__ x,
                                                   const float* __restrict__ xiw,
                                                   const float* __restrict__ xib) {
    __shared__ float xs[16*256];   // [c][2r] -- each x scalar duplicated
    __shared__ float ws[16*128];   // [c][k]
    int tid = threadIdx.x;
    int tx = tid & 15, ty = tid >> 4;
    size_t row0 = (size_t)blockIdx.x * 128;

    unsigned long long acc[8][4];
#pragma unroll
    for (int i = 0; i < 8; i++)
#pragma unroll
        for (int j = 0; j < 4; j++) acc[i][j] = 0ull;

    for (int cc = 0; cc < C; cc += 16) {
        for (int lin = tid; lin < 2048; lin += 256) {
            int r = lin >> 4, c = lin & 15;
            float vx = x[(row0 + r)*C + cc + c];
            xs[c*256 + 2*r]     = vx;
            xs[c*256 + 2*r + 1] = vx;
        }
        for (int lin = tid; lin < 2048; lin += 256) {
            int c = lin >> 7, kk = lin & 127;
            ws[lin] = xiw[(cc + c)*K + kk];
        }
        __syncthreads();
#pragma unroll
        for (int c = 0; c < 16; c++) {
            // 8 dup-pairs (rows ty*8..ty*8+7) via 4x LDS.128 (broadcast groups)
            ulonglong2 a01 = *(const ulonglong2*)&xs[c*256 + ty*16];
            ulonglong2 a23 = *(const ulonglong2*)&xs[c*256 + ty*16 + 4];
            ulonglong2 a45 = *(const ulonglong2*)&xs[c*256 + ty*16 + 8];
            ulonglong2 a67 = *(const ulonglong2*)&xs[c*256 + ty*16 + 12];
            // 4 w-pairs (cols tx*8..tx*8+7) via 2x LDS.128
            ulonglong2 w01 = *(const ulonglong2*)&ws[c*128 + tx*8];
            ulonglong2 w23 = *(const ulonglong2*)&ws[c*128 + tx*8 + 4];
            unsigned long long av[8] = {a01.x, a01.y, a23.x, a23.y,
                                        a45.x, a45.y, a67.x, a67.y};
            unsigned long long wv[4] = {w01.x, w01.y, w23.x, w23.y};
#pragma unroll
            for (int i = 0; i < 8; i++) {
                acc[i][0] = fma2(av[i], wv[0], acc[i][0]);
                acc[i][1] = fma2(av[i], wv[1], acc[i][1]);
                acc[i][2] = fma2(av[i], wv[2], acc[i][2]);
                acc[i][3] = fma2(av[i], wv[3], acc[i][3]);
            }
        }
        __syncthreads();
    }

    float4 b0 = *(const float4*)&xib[tx*8];
    float4 b1 = *(const float4*)&xib[tx*8 + 4];
#pragma unroll
    for (int i = 0; i < 8; i++) {
        size_t row = row0 + ty*8 + i;
        float f0,f1,f2,f3,f4v,f5,f6,f7;
        unpack2(acc[i][0], f0, f1);
        unpack2(acc[i][1], f2, f3);
        unpack2(acc[i][2], f4v, f5);
        unpack2(acc[i][3], f6, f7);
        float4 o0, o1;
        o0.x = f0 + b0.x; o0.y = f1 + b0.y; o0.z = f2 + b0.z; o0.w = f3 + b0.w;
        o1.x = f4v + b1.x; o1.y = f5 + b1.y; o1.z = f6 + b1.z; o1.w = f7 + b1.w;
        *(float4*)&g_H[row*K + tx*8]     = o0;
        *(float4*)&g_H[row*K + tx*8 + 4] = o1;
    }
}

// ---------------- K6: Z_G = gate*(A_tilde . H) + LayerNorm (f32x2) ----------
#define TT 8
__global__ void __launch_bounds__(512, 1) k6_zg_ln(const float* __restrict__ l2w,
                                                   const float* __restrict__ l2b,
                                                   float* __restrict__ out) {
    extern __shared__ float sm6[];
    float* Hs   = sm6;                 // 200*128 = 25600
    float* As0  = Hs  + 25600;         // 3200
    float* As1  = As0 + 3200;          // 3200
    float* mu_s = As1 + 3200;          // 200
    float* rs_s = mu_s + 200;          // 200

    int b  = blockIdx.x >> 4;
    int tt = blockIdx.x & 15;
    int tid = threadIdx.x;
    int kp = tid & 63;                 // k-pair index (k = 2*kp, 2*kp+1)
    int tg = tid >> 6;                 // local t (0..7)

    const size_t base = ((size_t)(b*T + tt*TT))*V*K;

    for (int lin = tid; lin < TT*V*K; lin += 512)
        Hs[lin] = g_H[base + lin];

    const float* Ab = g_Atil + (size_t)b*V*V*K;
    for (int lin = tid; lin < V*K; lin += 512) {
        int u = lin >> 7, kk = lin & 127;
        As0[lin] = Ab[((size_t)u*V + 0)*K + kk];
    }
    __syncthreads();

    unsigned long long z[V];
#pragma unroll
    for (int u = 0; u < V; u++) z[u] = 0ull;

    for (int v = 0; v < V; v++) {
        float* cur = (v & 1) ? As1 : As0;
        float* nxt = (v & 1) ? As0 : As1;
        if (v + 1 < V) {
            for (int lin = tid; lin < V*K; lin += 512) {
                int u = lin >> 7, kk = lin & 127;
                nxt[lin] = Ab[((size_t)u*V + (v+1))*K + kk];
            }
        }
        unsigned long long h = *(const unsigned long long*)&Hs[(tg*V + v)*K + 2*kp];
#pragma unroll
        for (int u = 0; u < V; u++) {
            unsigned long long a = *(const unsigned long long*)&cur[u*K + 2*kp];
            z[u] = fma2(h, a, z[u]);
        }
        __syncthreads();
    }

    // gate and write Z back to Hs (H no longer needed)
    float2 gk = *(const float2*)&g_gate[b*K + 2*kp];
#pragma unroll
    for (int u = 0; u < V; u++) {
        float zl, zh;
        unpack2(z[u], zl, zh);
        Hs[(tg*V + u)*K + 2*kp]     = zl * gk.x;
        Hs[(tg*V + u)*K + 2*kp + 1] = zh * gk.y;
    }
    __syncthreads();

    // LayerNorm stats (rotated k-scan: conflict-free)
    for (int p = tid; p < TT*V; p += 512) {
        float s = 0.f, s2 = 0.f;
        for (int kk = 0; kk < K; kk++) {
            int k = (kk + p) & 127;
            float val = Hs[p*K + k];
            s += val; s2 += val*val;
        }
        float m = s * (1.0f/K);
        float var = s2 * (1.0f/K) - m*m;
        mu_s[p] = m;
        rs_s[p] = rsqrtf(var + 1e-5f);
    }
    __syncthreads();

    for (int lin = tid; lin < TT*V*K; lin += 512) {
        int r = lin >> 7, kk = lin & 127;
        float val = (Hs[lin] - mu_s[r]) * rs_s[r];
        out[base + lin] = val * l2w[kk] + l2b[kk];
    }
}

// ---------------- launch --------------------------------------------------
extern "C" void kernel_launch(void* const* d_in, const int* in_sizes, int n_in,
                              void* d_out, int out_size) {
    const float* x    = (const float*)d_in[0];
    const float* A    = (const float*)d_in[1];
    const float* lam  = (const float*)d_in[2];
    const float* phiw = (const float*)d_in[3];
    const float* phib = (const float*)d_in[4];
    const float* thw  = (const float*)d_in[5];
    const float* thb  = (const float*)d_in[6];
    const float* kapw = (const float*)d_in[7];
    const float* kapb = (const float*)d_in[8];
    const float* xiw  = (const float*)d_in[9];
    const float* xib  = (const float*)d_in[10];
    const float* qw   = (const float*)d_in[11];
    const float* qb   = (const float*)d_in[12];
    const float* kw   = (const float*)d_in[13];
    const float* kb   = (const float*)d_in[14];
    const float* c1w  = (const float*)d_in[15];
    const float* c1b  = (const float*)d_in[16];
    const float* l1w  = (const float*)d_in[17];
    const float* l1b  = (const float*)d_in[18];
    const float* c2w  = (const float*)d_in[19];
    const float* c2b  = (const float*)d_in[20];
    const float* l2w  = (const float*)d_in[21];
    const float* l2b  = (const float*)d_in[22];
    float* out = (float*)d_out;

    size_t sm2 = (size_t)(3200 + 16384) * 4;
    size_t sm3 = (size_t)(16384 + 32*FPAD) * 4;
    size_t sm4 = (size_t)(4*3200 + 2*4096 + 512 + 32) * 4;
    size_t sm6 = (size_t)(25600 + 3200 + 3200 + 200 + 200) * 4;

    cudaFuncSetAttribute(k2_small,  cudaFuncAttributeMaxDynamicSharedMemorySize, (int)sm2);
    cudaFuncSetAttribute(k3_atilde, cudaFuncAttributeMaxDynamicSharedMemorySize, (int)sm3);
    cudaFuncSetAttribute(k4_gate,   cudaFuncAttributeMaxDynamicSharedMemorySize, (int)sm4);
    cudaFuncSetAttribute(k6_zg_ln,  cudaFuncAttributeMaxDynamicSharedMemorySize, (int)sm6);

    k1_xbar<<<B*V, 128>>>(x);
    k2_small<<<B, 256, sm2>>>(phiw, phib, thw, thb, xiw, xib);
    k3_atilde<<<B*20, 256, sm3>>>(A, lam, kapw, kapb);
    k4_gate<<<B, 512, sm4>>>(qw, qb, kw, kb, c1w, c1b, l1w, l1b, c2w, c2b);
    k5_hgemm<<<(B*T*V)/128, 256>>>(x, xiw, xib);
    k6_zg_ln<<<B*16, 512, sm6>>>(l2w, l2b, out);
}